// round 6
// baseline (speedup 1.0000x reference)
#include <cuda_runtime.h>
#include <cuda_bf16.h>
#include <cstdint>

// Problem constants
#define CDIM   256
#define HW     1024           // 32*32
#define KCODE  1024
#define MTILE  64             // z rows per block
#define CBLK   32             // c per block pass
#define NCBLK  (CDIM / CBLK)  // 8
#define KCHUNK 256            // codes per chunk
#define NCHUNK (KCODE / KCHUNK)  // 4
#define NTHREADS 128

// dynamic smem (floats):
//   zt  : [CBLK][64]  row-permuted z tile           = 2048 floats
//   etd : 128 code-pair rows x 132 floats (dup e)   = 16896 floats
// epilogue reuses the region as eg[64*257].
#define ZT_FLOATS   (CBLK * 64)            // 2048
#define ETD_STRIDE  132
#define ETD_FLOATS  (128 * ETD_STRIDE)     // 16896
#define SMEM_FLOATS (ZT_FLOATS + ETD_FLOATS)
#define SMEM_BYTES  (SMEM_FLOATS * 4)      // 75776 B

__device__ float g_esq[KCODE];

// packed f32x2 FMA: each lane bitwise-identical to fma.rn.f32
__device__ __forceinline__ void ffma2(unsigned long long& acc,
                                      unsigned long long a,
                                      unsigned long long b) {
    asm("fma.rn.f32x2 %0, %1, %2, %0;" : "+l"(acc) : "l"(a), "l"(b));
}
__device__ __forceinline__ void unpack2(unsigned long long v, float& lo, float& hi) {
    asm("mov.b64 {%0, %1}, %2;" : "=f"(lo), "=f"(hi) : "l"(v));
}

// ---------------------------------------------------------------------------
// Kernel 0: e_sq[k] = sum_c emb[k][c]^2, SEQUENTIAL fp32 mul-then-add.
// ---------------------------------------------------------------------------
__global__ void vq_esq_kernel(const float* __restrict__ emb,
                              float* __restrict__ out, int out_size, int nz) {
    int k = blockIdx.x * blockDim.x + threadIdx.x;
    if (k < KCODE) {
        const float* e = emb + (size_t)k * CDIM;
        float s = 0.f;
        #pragma unroll 8
        for (int c = 0; c < CDIM; ++c) {
            float v = e[c];
            s = __fadd_rn(s, __fmul_rn(v, v));
        }
        g_esq[k] = s;
    }
    if (blockIdx.x == 0 && threadIdx.x == 0 && out_size > nz)
        out[nz] = 0.0f;
}

// ---------------------------------------------------------------------------
// Main kernel: 128 threads, 2 CTAs/SM. Per-thread tile 16 rows x 8 codes,
// 4 k-chunks of 256 codes; per chunk 8 c-blocks of 32 c. FFMA2 with
// pre-duplicated e operands, conflict-free permuted layouts.
// ---------------------------------------------------------------------------
__global__ __launch_bounds__(NTHREADS, 2)
void vq_main_kernel(const float* __restrict__ z,
                    const float* __restrict__ emb,
                    float* __restrict__ out, int out_size, int nz) {
    extern __shared__ float smem[];
    float* zt  = smem;                 // [c*64 + pos(m)]
    float* etd = smem + ZT_FLOATS;     // [r*132 + c*4 + q]
    float* eg  = smem;                 // epilogue: [m*257 + c] (reuses all)
    __shared__ unsigned long long red[MTILE];
    __shared__ float zsq_sm[MTILE];
    __shared__ float wsum[4];

    const int tid = threadIdx.x;
    const int tm  = tid & 3;           // 4 row groups of 16
    const int tk  = tid >> 2;          // 32 code groups of 8 (per chunk)
    const int b   = blockIdx.x >> 4;
    const int hw0 = (blockIdx.x & 15) * MTILE;

    const float* zbase = z + (size_t)b * CDIM * HW + hw0;

    if (tid < MTILE) { red[tid] = 0xFFFFFFFFFFFFFFFFull; zsq_sm[tid] = 0.f; }

    for (int chunk = 0; chunk < NCHUNK; ++chunk) {
        unsigned long long acc[8][8];  // [row-pair][code]: rows tm*16+2p,+1
        #pragma unroll
        for (int p = 0; p < 8; ++p)
            #pragma unroll
            for (int j = 0; j < 8; ++j) acc[p][j] = 0ull;

        for (int blk = 0; blk < NCBLK; ++blk) {
            const int c0 = blk * CBLK;
            __syncthreads();   // prior compute / fold done before refill

            // ---- fill zt: pos(m) = ((m>>2)&3)*16 + (m>>4)*4 + (m&3) --------
            #pragma unroll
            for (int it = 0; it < 4; ++it) {
                int lin = it * NTHREADS + tid;     // 512 float4
                int c   = lin >> 4;
                int m4  = lin & 15;                // m = 4*m4
                float4 v = *(const float4*)(zbase + (size_t)(c0 + c) * HW + m4 * 4);
                int pos = (m4 & 3) * 16 + (m4 >> 2) * 4;
                *(float4*)(zt + c * 64 + pos) = v;
            }

            // ---- fill etd: row r(kp) = (kp&3)*32 + (kp>>2); dup values -----
            {
                int kp = tid;                      // 128 code pairs this chunk
                int r  = (kp & 3) * 32 + (kp >> 2);
                const float* ea = emb +
                    (size_t)(chunk * KCHUNK + 2 * kp) * CDIM + c0;
                const float* eb = ea + CDIM;
                float* dst = etd + r * ETD_STRIDE;
                #pragma unroll
                for (int c4 = 0; c4 < 8; ++c4) {   // 8 float4 groups = 32 c
                    float4 a  = *(const float4*)(ea + c4 * 4);
                    float4 bq = *(const float4*)(eb + c4 * 4);
                    *(float4*)(dst + (c4 * 4 + 0) * 4) = make_float4(a.x, a.x, bq.x, bq.x);
                    *(float4*)(dst + (c4 * 4 + 1) * 4) = make_float4(a.y, a.y, bq.y, bq.y);
                    *(float4*)(dst + (c4 * 4 + 2) * 4) = make_float4(a.z, a.z, bq.z, bq.z);
                    *(float4*)(dst + (c4 * 4 + 3) * 4) = make_float4(a.w, a.w, bq.w, bq.w);
                }
            }
            __syncthreads();

            // ---- incremental z_sq (chunk 0 only; exact ascending-c order) --
            if (chunk == 0 && tid < MTILE) {
                int m = tid;
                int pos = ((m >> 2) & 3) * 16 + (m >> 4) * 4 + (m & 3);
                float s = zsq_sm[m];
                #pragma unroll 8
                for (int c = 0; c < CBLK; ++c) {
                    float v = zt[c * 64 + pos];
                    s = __fadd_rn(s, __fmul_rn(v, v));
                }
                zsq_sm[m] = s;
            }

            // ---- compute: 32 c iters, 8 conflict-free LDS.128 + 64 FFMA2 ---
            #pragma unroll 2
            for (int c = 0; c < CBLK; ++c) {
                unsigned long long zp[8];
                #pragma unroll
                for (int i = 0; i < 4; ++i) {
                    ulonglong2 zv = *(const ulonglong2*)
                        (zt + c * 64 + i * 16 + tm * 4);
                    zp[2 * i]     = zv.x;
                    zp[2 * i + 1] = zv.y;
                }
                #pragma unroll
                for (int jj = 0; jj < 4; ++jj) {
                    ulonglong2 ee = *(const ulonglong2*)
                        (etd + (jj * 32 + tk) * ETD_STRIDE + c * 4);
                    #pragma unroll
                    for (int p = 0; p < 8; ++p) {
                        ffma2(acc[p][2 * jj],     zp[p], ee.x);
                        ffma2(acc[p][2 * jj + 1], zp[p], ee.y);
                    }
                }
            }
        }
        __syncthreads();   // zsq_sm complete (chunk 0); compute done

        // ---- fold this chunk into per-row argmin ---------------------------
        // d = fl( fl(z_sq + e_sq) - fl(2*e_z) ); ascending chunk + strict <
        // + packed-key atomicMin => exact first-min tie-break.
        {
            float esql[8];
            #pragma unroll
            for (int j = 0; j < 8; ++j)
                esql[j] = __ldg(&g_esq[chunk * KCHUNK + tk * 8 + j]);

            #pragma unroll
            for (int p = 0; p < 8; ++p) {
                #pragma unroll
                for (int bb = 0; bb < 2; ++bb) {
                    int m = tm * 16 + 2 * p + bb;
                    float zsq = zsq_sm[m];
                    float best = 3.4e38f; int bidx = 0;
                    #pragma unroll
                    for (int j = 0; j < 8; ++j) {
                        float lo, hi; unpack2(acc[p][j], lo, hi);
                        float ez = bb ? hi : lo;
                        float u = __fadd_rn(zsq, esql[j]);
                        float d = __fsub_rn(u, __fmul_rn(2.0f, ez));
                        if (d < best) { best = d; bidx = chunk * KCHUNK + tk * 8 + j; }
                    }
                    unsigned u = __float_as_uint(best);
                    u = (u & 0x80000000u) ? ~u : (u | 0x80000000u);
                    unsigned long long key =
                        ((unsigned long long)u << 32) | (unsigned)bidx;
                    atomicMin(&red[m], key);
                }
            }
        }
    }
    __syncthreads();

    // ---- gather: eg[m*257 + c] = emb[idx[m]][c] ------------------------------
    #pragma unroll 4
    for (int it = 0; it < 128; ++it) {
        int m  = it >> 1;
        int cc = (it & 1) * NTHREADS + tid;
        int kb = (int)(red[m] & 0xFFFFFFFFull);
        eg[m * 257 + cc] = emb[(size_t)kb * CDIM + cc];
    }
    __syncthreads();

    // ---- write z_q (coalesced float4) + loss partial (z re-read from gmem) ---
    float lsum = 0.f;
    float* obase = out + (size_t)b * CDIM * HW + hw0;
    #pragma unroll 4
    for (int it = 0; it < 32; ++it) {
        int lin = it * NTHREADS + tid;       // 4096 float4
        int c   = lin >> 4;
        int m4  = lin & 15;
        float4 zv = *(const float4*)(zbase + (size_t)c * HW + m4 * 4);
        float e0 = eg[(m4 * 4 + 0) * 257 + c];
        float e1 = eg[(m4 * 4 + 1) * 257 + c];
        float e2 = eg[(m4 * 4 + 2) * 257 + c];
        float e3 = eg[(m4 * 4 + 3) * 257 + c];
        float d0 = e0 - zv.x, d1 = e1 - zv.y, d2 = e2 - zv.z, d3 = e3 - zv.w;
        lsum += d0 * d0 + d1 * d1 + d2 * d2 + d3 * d3;
        *(float4*)(obase + (size_t)c * HW + m4 * 4) = make_float4(e0, e1, e2, e3);
    }

    // ---- block-reduce loss, atomicAdd global ---------------------------------
    #pragma unroll
    for (int off = 16; off > 0; off >>= 1)
        lsum += __shfl_down_sync(0xFFFFFFFFu, lsum, off);
    if ((tid & 31) == 0) wsum[tid >> 5] = lsum;
    __syncthreads();
    if (tid == 0) {
        float t = wsum[0] + wsum[1] + wsum[2] + wsum[3];
        if (out_size > nz)
            atomicAdd(&out[nz], t * (1.25f / 16777216.0f));  // (1+BETA)*mean
    }
}

// ---------------------------------------------------------------------------
extern "C" void kernel_launch(void* const* d_in, const int* in_sizes, int n_in,
                              void* d_out, int out_size) {
    const float* z   = (const float*)d_in[0];
    const float* emb = (const float*)d_in[1];
    float* out = (float*)d_out;
    const int nz = in_sizes[0];   // 16777216 z_q elements

    static cudaError_t _attr = cudaFuncSetAttribute(
        vq_main_kernel, cudaFuncAttributeMaxDynamicSharedMemorySize, SMEM_BYTES);
    (void)_attr;

    vq_esq_kernel<<<4, 256>>>(emb, out, out_size, nz);
    vq_main_kernel<<<1024, NTHREADS, SMEM_BYTES>>>(z, emb, out, out_size, nz);
}